// round 16
// baseline (speedup 1.0000x reference)
#include <cuda_runtime.h>
#include <cuda_bf16.h>
#include <cstdint>
#include <cstddef>

#define S_LEN 2048
#define DIM   4096
#define NH    32
#define HD    128
#define BATCH 2
#define MTOT  (BATCH*S_LEN)

typedef unsigned long long u64;
typedef unsigned int u32;
typedef unsigned short u16;

// ---------------- helpers ----------------
__device__ __forceinline__ u32 smem_u32(const void* p){
    u32 a; asm("{ .reg .u64 t; cvta.to.shared.u64 t, %1; cvt.u32.u64 %0, t; }" : "=r"(a) : "l"(p));
    return a;
}
__device__ __forceinline__ void mma16816(float* c, const u32* a, const u32* b){
    asm volatile("mma.sync.aligned.m16n8k16.row.col.f32.bf16.bf16.f32 "
        "{%0,%1,%2,%3}, {%4,%5,%6,%7}, {%8,%9}, {%0,%1,%2,%3};"
        : "+f"(c[0]), "+f"(c[1]), "+f"(c[2]), "+f"(c[3])
        : "r"(a[0]), "r"(a[1]), "r"(a[2]), "r"(a[3]), "r"(b[0]), "r"(b[1]));
}
__device__ __forceinline__ void ldsm4(u32* r, u32 addr){
    asm volatile("ldmatrix.sync.aligned.m8n8.x4.shared.b16 {%0,%1,%2,%3}, [%4];"
        : "=r"(r[0]), "=r"(r[1]), "=r"(r[2]), "=r"(r[3]) : "r"(addr));
}
__device__ __forceinline__ void ldsm4t(u32* r, u32 addr){
    asm volatile("ldmatrix.sync.aligned.m8n8.x4.trans.shared.b16 {%0,%1,%2,%3}, [%4];"
        : "=r"(r[0]), "=r"(r[1]), "=r"(r[2]), "=r"(r[3]) : "r"(addr));
}
__device__ __forceinline__ void cpa16(u32 dst, const void* src){
    asm volatile("cp.async.cg.shared.global [%0], [%1], 16;" :: "r"(dst), "l"(src) : "memory");
}
__device__ __forceinline__ u32 pkbf(float a, float b){
    u16 ha = __bfloat16_as_ushort(__float2bfloat16_rn(a));
    u16 hb = __bfloat16_as_ushort(__float2bfloat16_rn(b));
    return (u32)ha | ((u32)hb << 16);
}
__device__ __forceinline__ void store_split(__nv_bfloat16* H, __nv_bfloat16* L,
                                            size_t idx, float a0, float a1){
    const __nv_bfloat16 h0 = __float2bfloat16_rn(a0);
    const __nv_bfloat16 h1 = __float2bfloat16_rn(a1);
    *(u32*)(H + idx) = (u32)__bfloat16_as_ushort(h0) | ((u32)__bfloat16_as_ushort(h1) << 16);
    *(u32*)(L + idx) = pkbf(a0 - __bfloat162float(h0), a1 - __bfloat162float(h1));
}

// ---------------- scratch ----------------
__device__ __nv_bfloat16 g_xh[(size_t)MTOT*DIM],  g_xl[(size_t)MTOT*DIM];
__device__ __nv_bfloat16 g_wqh[(size_t)DIM*DIM], g_wql[(size_t)DIM*DIM];
__device__ __nv_bfloat16 g_wkh[(size_t)DIM*DIM], g_wkl[(size_t)DIM*DIM];
__device__ __nv_bfloat16 g_wvh[(size_t)DIM*DIM], g_wvl[(size_t)DIM*DIM];
__device__ __nv_bfloat16 g_woh[(size_t)DIM*DIM], g_wol[(size_t)DIM*DIM];
__device__ __nv_bfloat16 g_qh[(size_t)MTOT*DIM], g_ql[(size_t)MTOT*DIM];
__device__ __nv_bfloat16 g_kh[(size_t)MTOT*DIM], g_kl[(size_t)MTOT*DIM];
__device__ __nv_bfloat16 g_vh[(size_t)MTOT*DIM], g_vl[(size_t)MTOT*DIM];
__device__ __nv_bfloat16 g_ah[(size_t)MTOT*DIM], g_al[(size_t)MTOT*DIM];

// ============ fused fp32 -> (bf16 hi, bf16 lo) split for all 5 arrays ============
__global__ __launch_bounds__(256)
void split_all(const float* __restrict__ s0, __nv_bfloat16* __restrict__ h0, __nv_bfloat16* __restrict__ l0_,
               const float* __restrict__ s1, __nv_bfloat16* __restrict__ h1, __nv_bfloat16* __restrict__ l1_,
               const float* __restrict__ s2, __nv_bfloat16* __restrict__ h2, __nv_bfloat16* __restrict__ l2_,
               const float* __restrict__ s3, __nv_bfloat16* __restrict__ h3, __nv_bfloat16* __restrict__ l3_,
               const float* __restrict__ s4, __nv_bfloat16* __restrict__ h4, __nv_bfloat16* __restrict__ l4_)
{
    const float* s; __nv_bfloat16 *h, *l;
    switch (blockIdx.y) {
        case 0: s = s0; h = h0; l = l0_; break;
        case 1: s = s1; h = h1; l = l1_; break;
        case 2: s = s2; h = h2; l = l2_; break;
        case 3: s = s3; h = h3; l = l3_; break;
        default: s = s4; h = h4; l = l4_; break;
    }
    const size_t i = ((size_t)blockIdx.x * 256 + threadIdx.x) * 4;
    float4 v = *(const float4*)(s + i);
    float xs[4] = { v.x, v.y, v.z, v.w };
    u16 hs[4], ls[4];
    #pragma unroll
    for (int j = 0; j < 4; j++) {
        __nv_bfloat16 hb = __float2bfloat16_rn(xs[j]);
        hs[j] = __bfloat16_as_ushort(hb);
        ls[j] = __bfloat16_as_ushort(__float2bfloat16_rn(xs[j] - __bfloat162float(hb)));
    }
    uint2 H, L;
    H.x = (u32)hs[0] | ((u32)hs[1] << 16);  H.y = (u32)hs[2] | ((u32)hs[3] << 16);
    L.x = (u32)ls[0] | ((u32)ls[1] << 16);  L.y = (u32)ls[2] | ((u32)ls[3] << 16);
    *(uint2*)(h + i) = H;
    *(uint2*)(l + i) = L;
}

// ============ GEMM core: 4-stage BK=16 pipeline, one sync/iter ============
// stage: 4 arrays (Ah Al Bh Bl), each 128 rows x 16 bf16, row stride 48 B (conflict-free)
#define TARR  (128*48)            // 6144 B per array
#define TSTG  (4*TARR)            // 24576 B per stage
#define GEMM_SMEM (4*TSTG)        // 98304 B

#define GEMM_PREFETCH16(kt, Ahp, Alp, Bhp, Blp) do {                             \
    const u32 sb = sbase + ((kt) & 3) * TSTG;                                    \
    const u32 sa = sb + (u32)(prow*48 + pcc*16);                                 \
    const size_t gA = (size_t)(brow*128 + prow)*DIM + (size_t)(kt)*16 + pcc*8;   \
    const size_t gB = (size_t)(bc*128   + prow)*DIM + (size_t)(kt)*16 + pcc*8;   \
    cpa16(sa,          (Ahp) + gA);                                              \
    cpa16(sa + TARR,   (Alp) + gA);                                              \
    cpa16(sa + 2*TARR, (Bhp) + gB);                                              \
    cpa16(sa + 3*TARR, (Blp) + gB);                                              \
    asm volatile("cp.async.commit_group;" ::: "memory");                         \
} while (0)

#define GEMM_MAINLOOP(Ahp, Alp, Bhp, Blp)                                        \
    const int prow = tid >> 1, pcc = tid & 1;                                    \
    GEMM_PREFETCH16(0, Ahp, Alp, Bhp, Blp);                                      \
    GEMM_PREFETCH16(1, Ahp, Alp, Bhp, Blp);                                      \
    GEMM_PREFETCH16(2, Ahp, Alp, Bhp, Blp);                                      \
    const int a_r = (lane & 15);                                                 \
    const int a_c16 = (lane >> 4) * 16;                                          \
    const int b_r = (lane & 7) + ((lane >> 4) * 8);                              \
    const int b_c16 = ((lane >> 3) & 1) * 16;                                    \
    _Pragma("unroll 1")                                                          \
    for (int kt = 0; kt < 256; kt++) {                                           \
        if (kt < 253) { asm volatile("cp.async.wait_group 2;" ::: "memory"); }   \
        else          { asm volatile("cp.async.wait_group 0;" ::: "memory"); }   \
        __syncthreads();                                                         \
        if (kt + 3 < 256) GEMM_PREFETCH16(kt + 3, Ahp, Alp, Bhp, Blp);           \
        const u32 aB  = sbase + (kt & 3) * TSTG;                                 \
        const u32 alB = aB + TARR;                                               \
        const u32 bhB = aB + 2*TARR;                                             \
        const u32 blB = aB + 3*TARR;                                             \
        u32 ahf[2][4], alf[2][4];                                                \
        _Pragma("unroll")                                                        \
        for (int mf = 0; mf < 2; mf++) {                                         \
            const u32 off = (u32)((wm*32 + mf*16 + a_r) * 48 + a_c16);           \
            ldsm4(ahf[mf], aB  + off);                                           \
            ldsm4(alf[mf], alB + off);                                           \
        }                                                                        \
        _Pragma("unroll")                                                        \
        for (int nf2 = 0; nf2 < 4; nf2++) {                                      \
            const u32 offb = (u32)((wn*64 + nf2*16 + b_r) * 48 + b_c16);         \
            u32 bhf[4], blf[4];                                                  \
            ldsm4(bhf, bhB + offb);                                              \
            ldsm4(blf, blB + offb);                                              \
            _Pragma("unroll")                                                    \
            for (int mf = 0; mf < 2; mf++) {                                     \
                _Pragma("unroll")                                                \
                for (int hh = 0; hh < 2; hh++) {                                 \
                    float* c = acc[mf][nf2*2 + hh];                              \
                    mma16816(c, ahf[mf], bhf + 2*hh);                            \
                    mma16816(c, alf[mf], bhf + 2*hh);                            \
                    mma16816(c, ahf[mf], blf + 2*hh);                            \
                }                                                                \
            }                                                                    \
        }                                                                        \
    }

// ============ Fused QKV GEMM + RoPE + split epilogue ============
__global__ __launch_bounds__(256, 2)
void gemm_qkv(const __nv_bfloat16* __restrict__ Ah, const __nv_bfloat16* __restrict__ Al,
              const __nv_bfloat16* __restrict__ Wqh, const __nv_bfloat16* __restrict__ Wql,
              const __nv_bfloat16* __restrict__ Wkh, const __nv_bfloat16* __restrict__ Wkl,
              const __nv_bfloat16* __restrict__ Wvh, const __nv_bfloat16* __restrict__ Wvl,
              __nv_bfloat16* __restrict__ Qh, __nv_bfloat16* __restrict__ Ql,
              __nv_bfloat16* __restrict__ Kh, __nv_bfloat16* __restrict__ Kl,
              __nv_bfloat16* __restrict__ Vh, __nv_bfloat16* __restrict__ Vl,
              const float* __restrict__ cosT, const float* __restrict__ sinT)
{
    extern __shared__ char dsm[];
    const u32 sbase = smem_u32(dsm);

    const int tid  = threadIdx.x;
    const int brow = blockIdx.y;
    const int which = blockIdx.x >> 5;
    const int bc    = blockIdx.x & 31;
    const int warp = tid >> 5, lane = tid & 31;
    const int wm = warp >> 1, wn = warp & 1;

    const __nv_bfloat16* Bh = (which == 0) ? Wqh : (which == 1) ? Wkh : Wvh;
    const __nv_bfloat16* Bl = (which == 0) ? Wql : (which == 1) ? Wkl : Wvl;

    float acc[2][8][4];
    #pragma unroll
    for (int i = 0; i < 2; i++)
        #pragma unroll
        for (int j = 0; j < 8; j++)
            #pragma unroll
            for (int q = 0; q < 4; q++) acc[i][j][q] = 0.0f;

    GEMM_MAINLOOP(Ah, Al, Bh, Bl)

    __nv_bfloat16* OH = (which == 0) ? Qh : (which == 1) ? Kh : Vh;
    __nv_bfloat16* OL = (which == 0) ? Ql : (which == 1) ? Kl : Vl;
    const float qs = (which == 0) ? 0.08838834764831845f : 1.0f;

    #pragma unroll
    for (int mf = 0; mf < 2; mf++) {
        #pragma unroll
        for (int nf = 0; nf < 8; nf++) {
            const int r0 = brow*128 + wm*32 + mf*16 + (lane >> 2);
            const int c0 = bc*128 + wn*64 + nf*8 + (lane & 3)*2;
            float a0 = acc[mf][nf][0], a1 = acc[mf][nf][1];
            float a2 = acc[mf][nf][2], a3 = acc[mf][nf][3];
            if (which < 2) {
                const int d2 = (c0 & (HD - 1)) >> 1;
                const int s0 = r0 & (S_LEN - 1);
                const int s1 = (r0 + 8) & (S_LEN - 1);
                const float cA = cosT[(s0 << 6) + d2], sA = sinT[(s0 << 6) + d2];
                const float cB = cosT[(s1 << 6) + d2], sB = sinT[(s1 << 6) + d2];
                float o0 = (a0 * cA - a1 * sA) * qs;
                float o1 = (a0 * sA + a1 * cA) * qs;
                float o2 = (a2 * cB - a3 * sB) * qs;
                float o3 = (a2 * sB + a3 * cB) * qs;
                a0 = o0; a1 = o1; a2 = o2; a3 = o3;
            }
            store_split(OH, OL, (size_t)r0 * DIM + c0, a0, a1);
            store_split(OH, OL, (size_t)(r0 + 8) * DIM + c0, a2, a3);
        }
    }
}

// ============ Output-projection GEMM (fp32 out) ============
__global__ __launch_bounds__(256, 2)
void gemm_out(const __nv_bfloat16* __restrict__ Ah, const __nv_bfloat16* __restrict__ Al,
              const __nv_bfloat16* __restrict__ Bh, const __nv_bfloat16* __restrict__ Bl,
              float* __restrict__ C)
{
    extern __shared__ char dsm[];
    const u32 sbase = smem_u32(dsm);

    const int tid  = threadIdx.x;
    const int brow = blockIdx.y;
    const int bc   = blockIdx.x;
    const int warp = tid >> 5, lane = tid & 31;
    const int wm = warp >> 1, wn = warp & 1;

    float acc[2][8][4];
    #pragma unroll
    for (int i = 0; i < 2; i++)
        #pragma unroll
        for (int j = 0; j < 8; j++)
            #pragma unroll
            for (int q = 0; q < 4; q++) acc[i][j][q] = 0.0f;

    GEMM_MAINLOOP(Ah, Al, Bh, Bl)

    #pragma unroll
    for (int mf = 0; mf < 2; mf++) {
        #pragma unroll
        for (int nf = 0; nf < 8; nf++) {
            const int r0 = brow*128 + wm*32 + mf*16 + (lane >> 2);
            const int c0 = bc*128 + wn*64 + nf*8 + (lane & 3)*2;
            float* p = C + (size_t)r0 * DIM + c0;
            *(float2*)p           = make_float2(acc[mf][nf][0], acc[mf][nf][1]);
            *(float2*)(p + 8*DIM) = make_float2(acc[mf][nf][2], acc[mf][nf][3]);
        }
    }
}

// ============ HMMA flash attention with K/V software pipeline ============
#define LDV 136
#define FARR (128*LDV*2)
#define FLASH_SMEM (6*FARR)

__global__ __launch_bounds__(256, 1)
void flash_hmma(const __nv_bfloat16* __restrict__ Qhg, const __nv_bfloat16* __restrict__ Qlg,
                const __nv_bfloat16* __restrict__ Khg, const __nv_bfloat16* __restrict__ Klg,
                const __nv_bfloat16* __restrict__ Vhg, const __nv_bfloat16* __restrict__ Vlg,
                __nv_bfloat16* __restrict__ Oh, __nv_bfloat16* __restrict__ Ol)
{
    extern __shared__ char fsm[];
    const u32 QH = smem_u32(fsm);
    const u32 QL = QH + FARR;
    const u32 KH = QH + 2*FARR;
    const u32 KL = QH + 3*FARR;
    const u32 VH = QH + 4*FARR;
    const u32 VL = QH + 5*FARR;

    const int tid = threadIdx.x;
    const int w = tid >> 5, lane = tid & 31;
    const int qi = (int)gridDim.x - 1 - (int)blockIdx.x;
    const int h = blockIdx.y, b = blockIdx.z;
    const int q0 = qi * 128;
    const int R = w * 16;

    const int qrow_l = (lane & 7) + ((lane >> 3) & 1) * 8;
    const int qcol_l = (lane >> 4) * 8;
    const int krow_l = (lane & 7) + (lane >> 4) * 8;
    const int kcol_l = ((lane >> 3) & 1) * 8;
    const int vrow_l = (lane & 7) + ((lane >> 3) & 1) * 8;
    const int vcol_l = (lane >> 4) * 8;

    const int ldrow = tid >> 1;
    const int ldc0  = (tid & 1) * 64;
    const u32 soff = (u32)(ldrow * LDV + ldc0) * 2;

    // Q load (group), then K0 load (group)
    {
        const size_t gq = ((size_t)(b * S_LEN + q0 + ldrow)) * DIM + h * HD + ldc0;
        #pragma unroll
        for (int j = 0; j < 8; j++) {
            cpa16(QH + soff + j*16, Qhg + gq + j*8);
            cpa16(QL + soff + j*16, Qlg + gq + j*8);
        }
        asm volatile("cp.async.commit_group;" ::: "memory");
        const size_t gk = ((size_t)(b * S_LEN + ldrow)) * DIM + h * HD + ldc0;
        #pragma unroll
        for (int j = 0; j < 8; j++) {
            cpa16(KH + soff + j*16, Khg + gk + j*8);
            cpa16(KL + soff + j*16, Klg + gk + j*8);
        }
        asm volatile("cp.async.commit_group;" ::: "memory");
    }

    float S[16][4], O[16][4];
    #pragma unroll
    for (int n = 0; n < 16; n++)
        #pragma unroll
        for (int j = 0; j < 4; j++) O[n][j] = 0.0f;
    float m0 = -1e30f, m1 = -1e30f, l0 = 0.0f, l1 = 0.0f;

    #pragma unroll 1
    for (int kt = 0; kt <= qi; kt++) {
        __syncthreads();   // V (and K) smem free: prior tile's readers done
        {   // issue V_t
            const size_t gv = ((size_t)(b * S_LEN + kt * 128 + ldrow)) * DIM + h * HD + ldc0;
            #pragma unroll
            for (int j = 0; j < 8; j++) {
                cpa16(VH + soff + j*16, Vhg + gv + j*8);
                cpa16(VL + soff + j*16, Vlg + gv + j*8);
            }
            asm volatile("cp.async.commit_group;" ::: "memory");
        }
        // wait K_t (all groups except newest V_t)
        asm volatile("cp.async.wait_group 1;" ::: "memory");
        __syncthreads();

        // ---- S = Q K^T (3-term) ----
        #pragma unroll
        for (int n = 0; n < 16; n++)
            #pragma unroll
            for (int j = 0; j < 4; j++) S[n][j] = 0.0f;

        #pragma unroll
        for (int ks = 0; ks < 8; ks++) {
            u32 qh[4], ql[4];
            const u32 qoff = (u32)((R + qrow_l) * LDV + ks * 16 + qcol_l) * 2;
            ldsm4(qh, QH + qoff);
            ldsm4(ql, QL + qoff);
            #pragma unroll
            for (int n2 = 0; n2 < 8; n2++) {
                u32 kh[4], kl[4];
                const u32 koff = (u32)((n2 * 16 + krow_l) * LDV + ks * 16 + kcol_l) * 2;
                ldsm4(kh, KH + koff);
                ldsm4(kl, KL + koff);
                mma16816(S[2*n2],     qh, kh);     mma16816(S[2*n2],     ql, kh);     mma16816(S[2*n2],     qh, kl);
                mma16816(S[2*n2 + 1], qh, kh + 2); mma16816(S[2*n2 + 1], ql, kh + 2); mma16816(S[2*n2 + 1], qh, kl + 2);
            }
        }

        if (kt == qi) {
            const int r_lo = R + (lane >> 2);
            #pragma unroll
            for (int n = 0; n < 16; n++) {
                const int c = n * 8 + (lane & 3) * 2;
                if (c     > r_lo)     S[n][0] = -1e30f;
                if (c + 1 > r_lo)     S[n][1] = -1e30f;
                if (c     > r_lo + 8) S[n][2] = -1e30f;
                if (c + 1 > r_lo + 8) S[n][3] = -1e30f;
            }
        }

        // ---- online softmax (overlapped with V_t in flight) ----
        {
            float mx0 = -1e30f, mx1 = -1e30f;
            #pragma unroll
            for (int n = 0; n < 16; n++) {
                mx0 = fmaxf(mx0, fmaxf(S[n][0], S[n][1]));
                mx1 = fmaxf(mx1, fmaxf(S[n][2], S[n][3]));
            }
            mx0 = fmaxf(mx0, __shfl_xor_sync(0xffffffffu, mx0, 1));
            mx0 = fmaxf(mx0, __shfl_xor_sync(0xffffffffu, mx0, 2));
            mx1 = fmaxf(mx1, __shfl_xor_sync(0xffffffffu, mx1, 1));
            mx1 = fmaxf(mx1, __shfl_xor_sync(0xffffffffu, mx1, 2));

            const float m0n = fmaxf(m0, mx0);
            const float m1n = fmaxf(m1, mx1);
            const float f0 = __expf(m0 - m0n);
            const float f1 = __expf(m1 - m1n);

            float s0 = 0.0f, s1 = 0.0f;
            #pragma unroll
            for (int n = 0; n < 16; n++) {
                S[n][0] = __expf(S[n][0] - m0n); s0 += S[n][0];
                S[n][1] = __expf(S[n][1] - m0n); s0 += S[n][1];
                S[n][2] = __expf(S[n][2] - m1n); s1 += S[n][2];
                S[n][3] = __expf(S[n][3] - m1n); s1 += S[n][3];
            }
            s0 += __shfl_xor_sync(0xffffffffu, s0, 1);
            s0 += __shfl_xor_sync(0xffffffffu, s0, 2);
            s1 += __shfl_xor_sync(0xffffffffu, s1, 1);
            s1 += __shfl_xor_sync(0xffffffffu, s1, 2);

            l0 = l0 * f0 + s0;  l1 = l1 * f1 + s1;
            m0 = m0n;           m1 = m1n;

            #pragma unroll
            for (int n = 0; n < 16; n++) {
                O[n][0] *= f0;  O[n][1] *= f0;
                O[n][2] *= f1;  O[n][3] *= f1;
            }
        }

        // wait V_t; barrier so all threads' V is visible; then prefetch K_{t+1}
        asm volatile("cp.async.wait_group 0;" ::: "memory");
        __syncthreads();
        if (kt < qi) {
            const size_t gk = ((size_t)(b * S_LEN + (kt + 1) * 128 + ldrow)) * DIM + h * HD + ldc0;
            #pragma unroll
            for (int j = 0; j < 8; j++) {
                cpa16(KH + soff + j*16, Khg + gk + j*8);
                cpa16(KL + soff + j*16, Klg + gk + j*8);
            }
            asm volatile("cp.async.commit_group;" ::: "memory");
        }

        // ---- O += P V (3-term) ----
        #pragma unroll
        for (int ks = 0; ks < 8; ks++) {
            u32 ph[4], pl[4];
            #pragma unroll
            for (int t = 0; t < 4; t++) {
                const int n = 2*ks + (t >> 1);
                const int j0 = (t & 1) * 2;
                const float p0 = S[n][j0], p1 = S[n][j0 + 1];
                const __nv_bfloat16 h0 = __float2bfloat16_rn(p0);
                const __nv_bfloat16 h1 = __float2bfloat16_rn(p1);
                ph[t] = (u32)__bfloat16_as_ushort(h0) | ((u32)__bfloat16_as_ushort(h1) << 16);
                pl[t] = pkbf(p0 - __bfloat162float(h0), p1 - __bfloat162float(h1));
            }
            #pragma unroll
            for (int n2 = 0; n2 < 8; n2++) {
                u32 vh[4], vl[4];
                const u32 voff = (u32)((ks * 16 + vrow_l) * LDV + n2 * 16 + vcol_l) * 2;
                ldsm4t(vh, VH + voff);
                ldsm4t(vl, VL + voff);
                mma16816(O[2*n2],     ph, vh);     mma16816(O[2*n2],     pl, vh);     mma16816(O[2*n2],     ph, vl);
                mma16816(O[2*n2 + 1], ph, vh + 2); mma16816(O[2*n2 + 1], pl, vh + 2); mma16816(O[2*n2 + 1], ph, vl + 2);
            }
        }
    }

    // ---- epilogue ----
    {
        const float inv0 = 1.0f / l0;
        const float inv1 = 1.0f / l1;
        const size_t row0 = (size_t)(b * S_LEN + q0 + R + (lane >> 2));
        const size_t row1 = row0 + 8;
        const int colb = h * HD + (lane & 3) * 2;
        #pragma unroll
        for (int n = 0; n < 16; n++) {
            const int col = colb + n * 8;
            store_split(Oh, Ol, row0 * DIM + col, O[n][0] * inv0, O[n][1] * inv0);
            store_split(Oh, Ol, row1 * DIM + col, O[n][2] * inv1, O[n][3] * inv1);
        }
    }
}

extern "C" void kernel_launch(void* const* d_in, const int* in_sizes, int n_in,
                              void* d_out, int out_size)
{
    const float* x  = (const float*)d_in[0];
    const float* wq = (const float*)d_in[1];
    const float* wk = (const float*)d_in[2];
    const float* wv = (const float*)d_in[3];
    const float* wo = (const float*)d_in[4];
    const float* fc = (const float*)d_in[5];
    const float* fs = (const float*)d_in[6];
    float* out = (float*)d_out;

    __nv_bfloat16 *xh, *xl, *wqh, *wql, *wkh, *wkl, *wvh, *wvl, *woh, *wol;
    __nv_bfloat16 *qh, *ql, *kh, *kl, *vh, *vl, *ah, *al;
    cudaGetSymbolAddress((void**)&xh,  g_xh);   cudaGetSymbolAddress((void**)&xl,  g_xl);
    cudaGetSymbolAddress((void**)&wqh, g_wqh);  cudaGetSymbolAddress((void**)&wql, g_wql);
    cudaGetSymbolAddress((void**)&wkh, g_wkh);  cudaGetSymbolAddress((void**)&wkl, g_wkl);
    cudaGetSymbolAddress((void**)&wvh, g_wvh);  cudaGetSymbolAddress((void**)&wvl, g_wvl);
    cudaGetSymbolAddress((void**)&woh, g_woh);  cudaGetSymbolAddress((void**)&wol, g_wol);
    cudaGetSymbolAddress((void**)&qh,  g_qh);   cudaGetSymbolAddress((void**)&ql,  g_ql);
    cudaGetSymbolAddress((void**)&kh,  g_kh);   cudaGetSymbolAddress((void**)&kl,  g_kl);
    cudaGetSymbolAddress((void**)&vh,  g_vh);   cudaGetSymbolAddress((void**)&vl,  g_vl);
    cudaGetSymbolAddress((void**)&ah,  g_ah);   cudaGetSymbolAddress((void**)&al,  g_al);

    cudaFuncSetAttribute(gemm_qkv,  cudaFuncAttributeMaxDynamicSharedMemorySize, GEMM_SMEM);
    cudaFuncSetAttribute(gemm_out,  cudaFuncAttributeMaxDynamicSharedMemorySize, GEMM_SMEM);
    cudaFuncSetAttribute(flash_hmma, cudaFuncAttributeMaxDynamicSharedMemorySize, FLASH_SMEM);

    dim3 gs((DIM * DIM / 4) / 256, 5);
    split_all<<<gs, 256>>>(x, xh, xl, wq, wqh, wql, wk, wkh, wkl,
                           wv, wvh, wvl, wo, woh, wol);

    dim3 gq(96, 32);
    gemm_qkv<<<gq, 256, GEMM_SMEM>>>(xh, xl, wqh, wql, wkh, wkl, wvh, wvl,
                                     qh, ql, kh, kl, vh, vl, fc, fs);

    dim3 ga(S_LEN / 128, NH, BATCH);
    flash_hmma<<<ga, 256, FLASH_SMEM>>>(qh, ql, kh, kl, vh, vl, ah, al);

    dim3 gt(32, 32);
    gemm_out<<<gt, 256, GEMM_SMEM>>>(ah, al, woh, wol, out);
}